// round 3
// baseline (speedup 1.0000x reference)
#include <cuda_runtime.h>
#include <math.h>

#define N_NODES 50000
#define E_EDGES 800000
#define E_TOT   850000   // + self loops
#define HEADS   4
#define HID     64
#define FDIM    256      // HEADS*HID
#define INDIM   128
#define OUTDIM  10
#define NEG_SLOPE 0.2f

// ---------------- scratch (device globals; no allocations allowed) ----------
static __device__ __align__(16) float g_hbuf[N_NODES * FDIM];   // projected features [N,256]
static __device__ __align__(16) float g_feat[N_NODES * HID];    // layer output [N,64]
static __device__ __align__(16) float g_als[N_NODES * HEADS];
static __device__ __align__(16) float g_ald[N_NODES * HEADS];
static __device__ int   g_rowptr[N_NODES + 1];
static __device__ int   g_wrcur[N_NODES];
static __device__ int   g_deg[N_NODES];
static __device__ int   g_csrc[E_TOT];
static __device__ int   g_is64;     // 1 if edge_index is int64, 0 if int32

// ---------------- helpers ----------------
__device__ __forceinline__ float lrelu(float x) {
    return x >= 0.f ? x : NEG_SLOPE * x;
}

__device__ __forceinline__ unsigned long long pack2(float x) {
    unsigned long long r;
    unsigned int u = __float_as_uint(x);
    asm("mov.b64 %0, {%1, %1};" : "=l"(r) : "r"(u));
    return r;
}
__device__ __forceinline__ void ffma2(unsigned long long &c,
                                      unsigned long long a,
                                      unsigned long long b) {
    asm("fma.rn.f32x2 %0, %1, %2, %0;" : "+l"(c) : "l"(a), "l"(b));
}
__device__ __forceinline__ void unpack2(unsigned long long c, float &lo, float &hi) {
    unsigned int ulo, uhi;
    asm("mov.b64 {%0, %1}, %2;" : "=r"(ulo), "=r"(uhi) : "l"(c));
    lo = __uint_as_float(ulo);
    hi = __uint_as_float(uhi);
}

// read edge index element (which: 0 = src row, 1 = dst row)
__device__ __forceinline__ int load_idx(const void* ei, int which, int e) {
    if (g_is64) {
        long long v = ((const long long*)ei)[(size_t)which * E_EDGES + e];
        return (int)v;
    } else {
        return ((const int*)ei)[(size_t)which * E_EDGES + e];
    }
}

// ---------------- dtype probe ----------------
// If the first 256 values interpreted as int64 are all in [0, N), it's int64.
// For int32 data, each int64 read fuses two random indices -> high word almost
// surely nonzero -> out of range.
__global__ void k_probe(const void* __restrict__ ei) {
    __shared__ int bad;
    if (threadIdx.x == 0) bad = 0;
    __syncthreads();
    const long long* p = (const long long*)ei;
    long long v = p[threadIdx.x];
    if (v < 0 || v >= N_NODES) atomicOr(&bad, 1);
    __syncthreads();
    if (threadIdx.x == 0) g_is64 = bad ? 0 : 1;
}

// ---------------- CSR build ----------------
__global__ void k_deg_init() {
    int i = blockIdx.x * 256 + threadIdx.x;
    if (i < N_NODES) g_deg[i] = 1;   // self loop
}

__global__ void k_hist(const void* __restrict__ ei) {
    int e = blockIdx.x * 256 + threadIdx.x;
    if (e < E_EDGES) {
        int d = load_idx(ei, 1, e);
        if ((unsigned)d < N_NODES) atomicAdd(&g_deg[d], 1);
    }
}

// single-block exclusive scan over g_deg -> g_rowptr, g_wrcur
__global__ void k_scan() {
    __shared__ int ws[32];
    int tid = threadIdx.x;
    int lane = tid & 31, warp = tid >> 5;
    int carry = 0;
    for (int base = 0; base < N_NODES; base += 1024) {
        int i = base + tid;
        int v = (i < N_NODES) ? g_deg[i] : 0;
        int x = v;
        #pragma unroll
        for (int off = 1; off < 32; off <<= 1) {
            int t = __shfl_up_sync(0xffffffffu, x, off);
            if (lane >= off) x += t;
        }
        if (lane == 31) ws[warp] = x;
        __syncthreads();
        if (warp == 0) {
            int s = ws[lane];
            #pragma unroll
            for (int off = 1; off < 32; off <<= 1) {
                int t = __shfl_up_sync(0xffffffffu, s, off);
                if (lane >= off) s += t;
            }
            ws[lane] = s;
        }
        __syncthreads();
        int woff = warp ? ws[warp - 1] : 0;
        int excl = carry + woff + x - v;
        if (i < N_NODES) { g_rowptr[i] = excl; g_wrcur[i] = excl; }
        int tot = ws[31];
        __syncthreads();
        carry += tot;
    }
    if (tid == 0) g_rowptr[N_NODES] = carry;
}

__global__ void k_fill(const void* __restrict__ ei) {
    int e = blockIdx.x * 256 + threadIdx.x;
    if (e >= E_TOT) return;
    int s, d;
    if (e < E_EDGES) {
        s = load_idx(ei, 0, e);
        d = load_idx(ei, 1, e);
    } else {
        s = d = e - E_EDGES;
    }
    if ((unsigned)s >= N_NODES || (unsigned)d >= N_NODES) return;
    int pos = atomicAdd(&g_wrcur[d], 1);
    if ((unsigned)pos < E_TOT) g_csrc[pos] = s;
}

// ---------------- GEMM: C[N,256] = A[N,K] @ W[K,256] (fp32, packed f32x2) ---
// BM=64, BN=128, BK=16, 256 threads, per-thread 4x8 micro-tile (as 4x4 f32x2)
__global__ void __launch_bounds__(256) k_gemm(const float* __restrict__ xin,
                                              int use_feat,
                                              const float* __restrict__ W,
                                              int M, int K) {
    const float* A = use_feat ? g_feat : xin;
    __shared__ float As[16][65];
    __shared__ float Bs[16][128];
    int tid = threadIdx.x;
    int tx = tid & 15;   // n-group
    int ty = tid >> 4;   // m-group
    int bm = blockIdx.y * 64;
    int bn = blockIdx.x * 128;

    unsigned long long c[4][4];
    #pragma unroll
    for (int i = 0; i < 4; i++)
        #pragma unroll
        for (int j = 0; j < 4; j++) c[i][j] = 0ull;

    int arow = tid >> 2;            // 0..63
    int acol = (tid & 3) * 4;       // 0,4,8,12
    int bk   = tid >> 4;            // 0..15
    int bnc  = (tid & 15) * 8;      // 0..120

    for (int k0 = 0; k0 < K; k0 += 16) {
        float4 av = make_float4(0.f, 0.f, 0.f, 0.f);
        int gr = bm + arow;
        if (gr < M) av = *(const float4*)(A + (size_t)gr * K + k0 + acol);
        As[acol + 0][arow] = av.x;
        As[acol + 1][arow] = av.y;
        As[acol + 2][arow] = av.z;
        As[acol + 3][arow] = av.w;

        const float* bp = W + (size_t)(k0 + bk) * FDIM + bn + bnc;
        *(float4*)&Bs[bk][bnc]     = *(const float4*)bp;
        *(float4*)&Bs[bk][bnc + 4] = *(const float4*)(bp + 4);
        __syncthreads();

        #pragma unroll
        for (int k = 0; k < 16; k++) {
            unsigned long long aP[4];
            #pragma unroll
            for (int i = 0; i < 4; i++) aP[i] = pack2(As[k][ty * 4 + i]);
            unsigned long long bq[4];
            #pragma unroll
            for (int j = 0; j < 4; j++)
                bq[j] = *(const unsigned long long*)&Bs[k][tx * 2 + 32 * j];
            #pragma unroll
            for (int i = 0; i < 4; i++)
                #pragma unroll
                for (int j = 0; j < 4; j++) ffma2(c[i][j], aP[i], bq[j]);
        }
        __syncthreads();
    }

    #pragma unroll
    for (int i = 0; i < 4; i++) {
        int gr = bm + ty * 4 + i;
        if (gr < M) {
            #pragma unroll
            for (int j = 0; j < 4; j++) {
                float lo, hi;
                unpack2(c[i][j], lo, hi);
                float2 v2 = make_float2(lo, hi);
                *(float2*)(g_hbuf + (size_t)gr * FDIM + bn + tx * 2 + 32 * j) = v2;
            }
        }
    }
}

// ---------------- attention logits: als/ald [N,4] ----------------
__global__ void __launch_bounds__(128) k_attn(const float* __restrict__ asrc,
                                              const float* __restrict__ adst) {
    int v = blockIdx.x;
    int tid = threadIdx.x;
    int h = tid >> 5, lane = tid & 31;
    const float* hb = g_hbuf + (size_t)v * FDIM + h * HID;
    float x0 = hb[lane], x1 = hb[lane + 32];
    float s = x0 * asrc[h * HID + lane] + x1 * asrc[h * HID + lane + 32];
    float d = x0 * adst[h * HID + lane] + x1 * adst[h * HID + lane + 32];
    #pragma unroll
    for (int off = 16; off >= 1; off >>= 1) {
        s += __shfl_xor_sync(0xffffffffu, s, off);
        d += __shfl_xor_sync(0xffffffffu, d, off);
    }
    if (lane == 0) {
        g_als[v * HEADS + h] = s;
        g_ald[v * HEADS + h] = d;
    }
}

// ---------------- softmax + aggregation: one block per dst node -------------
__global__ void __launch_bounds__(256) k_agg(const float* __restrict__ bias) {
    int v = blockIdx.x;
    int tid = threadIdx.x, lane = tid & 31, warp = tid >> 5;
    int beg = g_rowptr[v];
    int deg = g_rowptr[v + 1] - beg;

    __shared__ float s_red[32];
    __shared__ float s_m[4], s_inv[4];
    __shared__ int    s_src[256];
    __shared__ float4 s_alpha[256];
    __shared__ float  s_acc[256];

    float4 aldv = *(const float4*)(g_ald + v * 4);

    // phase 1: per-head max over incoming edges
    float m0 = -1e30f, m1 = -1e30f, m2 = -1e30f, m3 = -1e30f;
    for (int j = tid; j < deg; j += 256) {
        float4 as = *(const float4*)(g_als + g_csrc[beg + j] * 4);
        m0 = fmaxf(m0, lrelu(as.x + aldv.x));
        m1 = fmaxf(m1, lrelu(as.y + aldv.y));
        m2 = fmaxf(m2, lrelu(as.z + aldv.z));
        m3 = fmaxf(m3, lrelu(as.w + aldv.w));
    }
    #pragma unroll
    for (int off = 16; off >= 1; off >>= 1) {
        m0 = fmaxf(m0, __shfl_xor_sync(0xffffffffu, m0, off));
        m1 = fmaxf(m1, __shfl_xor_sync(0xffffffffu, m1, off));
        m2 = fmaxf(m2, __shfl_xor_sync(0xffffffffu, m2, off));
        m3 = fmaxf(m3, __shfl_xor_sync(0xffffffffu, m3, off));
    }
    if (lane == 0) {
        s_red[warp * 4 + 0] = m0; s_red[warp * 4 + 1] = m1;
        s_red[warp * 4 + 2] = m2; s_red[warp * 4 + 3] = m3;
    }
    __syncthreads();
    if (tid < 4) {
        float m = -1e30f;
        #pragma unroll
        for (int w = 0; w < 8; w++) m = fmaxf(m, s_red[w * 4 + tid]);
        s_m[tid] = m;
    }
    __syncthreads();
    m0 = s_m[0]; m1 = s_m[1]; m2 = s_m[2]; m3 = s_m[3];
    __syncthreads();

    // phase 2: per-head sum of exp(e - m)
    float t0 = 0.f, t1 = 0.f, t2 = 0.f, t3 = 0.f;
    for (int j = tid; j < deg; j += 256) {
        float4 as = *(const float4*)(g_als + g_csrc[beg + j] * 4);
        t0 += __expf(lrelu(as.x + aldv.x) - m0);
        t1 += __expf(lrelu(as.y + aldv.y) - m1);
        t2 += __expf(lrelu(as.z + aldv.z) - m2);
        t3 += __expf(lrelu(as.w + aldv.w) - m3);
    }
    #pragma unroll
    for (int off = 16; off >= 1; off >>= 1) {
        t0 += __shfl_xor_sync(0xffffffffu, t0, off);
        t1 += __shfl_xor_sync(0xffffffffu, t1, off);
        t2 += __shfl_xor_sync(0xffffffffu, t2, off);
        t3 += __shfl_xor_sync(0xffffffffu, t3, off);
    }
    if (lane == 0) {
        s_red[warp * 4 + 0] = t0; s_red[warp * 4 + 1] = t1;
        s_red[warp * 4 + 2] = t2; s_red[warp * 4 + 3] = t3;
    }
    __syncthreads();
    if (tid < 4) {
        float s = 0.f;
        #pragma unroll
        for (int w = 0; w < 8; w++) s += s_red[w * 4 + tid];
        s_inv[tid] = 1.f / s;
    }
    __syncthreads();
    float i0 = s_inv[0], i1 = s_inv[1], i2 = s_inv[2], i3 = s_inv[3];

    // phase 3: acc[c] = sum_j alpha[j, head(c)] * h[src_j, c]
    float acc = 0.f;
    int c = tid;
    int hd = tid >> 6;
    for (int c0 = 0; c0 < deg; c0 += 256) {
        __syncthreads();
        int j = c0 + tid;
        if (j < deg) {
            int s = g_csrc[beg + j];
            float4 as = *(const float4*)(g_als + s * 4);
            float a0 = __expf(lrelu(as.x + aldv.x) - m0) * i0;
            float a1 = __expf(lrelu(as.y + aldv.y) - m1) * i1;
            float a2 = __expf(lrelu(as.z + aldv.z) - m2) * i2;
            float a3 = __expf(lrelu(as.w + aldv.w) - m3) * i3;
            s_src[tid] = s;
            s_alpha[tid] = make_float4(a0, a1, a2, a3);
        }
        __syncthreads();
        int nc = min(256, deg - c0);
        int jj = 0;
        for (; jj + 4 <= nc; jj += 4) {
            int sA = s_src[jj], sB = s_src[jj + 1], sC = s_src[jj + 2], sD = s_src[jj + 3];
            float aA = ((const float*)&s_alpha[jj])[hd];
            float aB = ((const float*)&s_alpha[jj + 1])[hd];
            float aC = ((const float*)&s_alpha[jj + 2])[hd];
            float aD = ((const float*)&s_alpha[jj + 3])[hd];
            float vA = g_hbuf[(size_t)sA * FDIM + c];
            float vB = g_hbuf[(size_t)sB * FDIM + c];
            float vC = g_hbuf[(size_t)sC * FDIM + c];
            float vD = g_hbuf[(size_t)sD * FDIM + c];
            acc = fmaf(aA, vA, acc);
            acc = fmaf(aB, vB, acc);
            acc = fmaf(aC, vC, acc);
            acc = fmaf(aD, vD, acc);
        }
        for (; jj < nc; jj++) {
            int s = s_src[jj];
            float a = ((const float*)&s_alpha[jj])[hd];
            acc = fmaf(a, g_hbuf[(size_t)s * FDIM + c], acc);
        }
    }
    s_acc[tid] = acc;
    __syncthreads();
    if (tid < HID) {
        float r = (s_acc[tid] + s_acc[tid + 64] + s_acc[tid + 128] + s_acc[tid + 192]) * 0.25f
                  + bias[tid];
        g_feat[v * HID + tid] = r > 0.f ? r : expm1f(r);   // ELU
    }
}

// ---------------- final FC: out[N,10] = feat @ fcW + fcb --------------------
__global__ void __launch_bounds__(256) k_fc(const float* __restrict__ W,
                                            const float* __restrict__ b,
                                            float* __restrict__ out) {
    __shared__ float sw[HID * OUTDIM];
    __shared__ float sb[OUTDIM];
    for (int i = threadIdx.x; i < HID * OUTDIM; i += 256) sw[i] = W[i];
    if (threadIdx.x < OUTDIM) sb[threadIdx.x] = b[threadIdx.x];
    __syncthreads();
    int t = blockIdx.x * 256 + threadIdx.x;
    if (t >= N_NODES * OUTDIM) return;
    int n = t / OUTDIM, o = t - n * OUTDIM;
    const float* f = g_feat + (size_t)n * HID;
    float acc = sb[o];
    #pragma unroll
    for (int k = 0; k < HID; k++) acc = fmaf(f[k], sw[k * OUTDIM + o], acc);
    out[t] = acc;
}

// ---------------- launch ----------------
extern "C" void kernel_launch(void* const* d_in, const int* in_sizes, int n_in,
                              void* d_out, int out_size) {
    const float* x   = (const float*)d_in[0];
    const void*  ei  = d_in[1];
    const float* Wl[3]   = { (const float*)d_in[2], (const float*)d_in[6],  (const float*)d_in[10] };
    const float* Asl[3]  = { (const float*)d_in[3], (const float*)d_in[7],  (const float*)d_in[11] };
    const float* Adl[3]  = { (const float*)d_in[4], (const float*)d_in[8],  (const float*)d_in[12] };
    const float* Bl[3]   = { (const float*)d_in[5], (const float*)d_in[9],  (const float*)d_in[13] };
    const float* fcW = (const float*)d_in[14];
    const float* fcb = (const float*)d_in[15];
    float* out = (float*)d_out;

    // dtype probe + CSR by destination (rebuilt every call; deterministic)
    k_probe<<<1, 256>>>(ei);
    k_deg_init<<<(N_NODES + 255) / 256, 256>>>();
    k_hist<<<(E_EDGES + 255) / 256, 256>>>(ei);
    k_scan<<<1, 1024>>>();
    k_fill<<<(E_TOT + 255) / 256, 256>>>(ei);

    for (int l = 0; l < 3; l++) {
        int K = (l == 0) ? INDIM : HID;
        dim3 g(FDIM / 128, (N_NODES + 63) / 64);
        k_gemm<<<g, 256>>>(x, l > 0 ? 1 : 0, Wl[l], N_NODES, K);
        k_attn<<<N_NODES, 128>>>(Asl[l], Adl[l]);
        k_agg<<<N_NODES, 256>>>(Bl[l]);
    }
    k_fc<<<(N_NODES * OUTDIM + 255) / 256, 256>>>(fcW, fcb, out);
}

// round 4
// speedup vs baseline: 1.3129x; 1.3129x over previous
#include <cuda_runtime.h>
#include <cuda_fp16.h>
#include <math.h>

#define N_NODES 50000
#define E_EDGES 800000
#define E_TOT   850000   // + self loops
#define HEADS   4
#define HID     64
#define FDIM    256      // HEADS*HID
#define FDIM2   128      // half2 elements per row
#define INDIM   128
#define OUTDIM  10
#define NEG_SLOPE 0.2f
#define SCAN_NB  ((N_NODES + 255) / 256)   // 196

// ---------------- scratch (device globals; no allocations allowed) ----------
static __device__ __align__(16) __half g_hbuf[N_NODES * FDIM];  // projected features [N,256] fp16
static __device__ __align__(16) float  g_feat[N_NODES * HID];   // layer output [N,64] fp32
static __device__ __align__(16) float  g_als[N_NODES * HEADS];
static __device__ __align__(16) float  g_ald[N_NODES * HEADS];
static __device__ int   g_rowptr[N_NODES + 1];
static __device__ int   g_wrcur[N_NODES];
static __device__ int   g_deg[N_NODES];
static __device__ int   g_csrc[E_TOT];
static __device__ int   g_blksum[SCAN_NB];
static __device__ int   g_blkoff[SCAN_NB];
static __device__ int   g_is64;     // 1 if edge_index is int64, 0 if int32

// ---------------- helpers ----------------
__device__ __forceinline__ float lrelu(float x) {
    return x >= 0.f ? x : NEG_SLOPE * x;
}

__device__ __forceinline__ unsigned long long pack2(float x) {
    unsigned long long r;
    unsigned int u = __float_as_uint(x);
    asm("mov.b64 %0, {%1, %1};" : "=l"(r) : "r"(u));
    return r;
}
__device__ __forceinline__ void ffma2(unsigned long long &c,
                                      unsigned long long a,
                                      unsigned long long b) {
    asm("fma.rn.f32x2 %0, %1, %2, %0;" : "+l"(c) : "l"(a), "l"(b));
}
__device__ __forceinline__ void unpack2(unsigned long long c, float &lo, float &hi) {
    unsigned int ulo, uhi;
    asm("mov.b64 {%0, %1}, %2;" : "=r"(ulo), "=r"(uhi) : "l"(c));
    lo = __uint_as_float(ulo);
    hi = __uint_as_float(uhi);
}

__device__ __forceinline__ int load_idx(const void* ei, int which, int e) {
    if (g_is64) {
        long long v = ((const long long*)ei)[(size_t)which * E_EDGES + e];
        return (int)v;
    } else {
        return ((const int*)ei)[(size_t)which * E_EDGES + e];
    }
}

// ---------------- dtype probe ----------------
__global__ void k_probe(const void* __restrict__ ei) {
    __shared__ int bad;
    if (threadIdx.x == 0) bad = 0;
    __syncthreads();
    const long long* p = (const long long*)ei;
    long long v = p[threadIdx.x];
    if (v < 0 || v >= N_NODES) atomicOr(&bad, 1);
    __syncthreads();
    if (threadIdx.x == 0) g_is64 = bad ? 0 : 1;
}

// ---------------- CSR build ----------------
__global__ void k_deg_init() {
    int i = blockIdx.x * 256 + threadIdx.x;
    if (i < N_NODES) g_deg[i] = 1;   // self loop
}

__global__ void k_hist(const void* __restrict__ ei) {
    int e = blockIdx.x * 256 + threadIdx.x;
    if (e < E_EDGES) {
        int d = load_idx(ei, 1, e);
        if ((unsigned)d < N_NODES) atomicAdd(&g_deg[d], 1);
    }
}

// scan stage A: per-block sums of g_deg
__global__ void __launch_bounds__(256) k_scanA() {
    __shared__ int sm[8];
    int i = blockIdx.x * 256 + threadIdx.x;
    int v = (i < N_NODES) ? g_deg[i] : 0;
    int lane = threadIdx.x & 31, warp = threadIdx.x >> 5;
    #pragma unroll
    for (int off = 16; off >= 1; off >>= 1) v += __shfl_xor_sync(0xffffffffu, v, off);
    if (lane == 0) sm[warp] = v;
    __syncthreads();
    if (threadIdx.x == 0) {
        int s = 0;
        #pragma unroll
        for (int w = 0; w < 8; w++) s += sm[w];
        g_blksum[blockIdx.x] = s;
    }
}

// scan stage B: exclusive scan over SCAN_NB block sums (single block, 256 thr)
__global__ void __launch_bounds__(256) k_scanB() {
    __shared__ int ws[8];
    int tid = threadIdx.x;
    int lane = tid & 31, warp = tid >> 5;
    int v = (tid < SCAN_NB) ? g_blksum[tid] : 0;
    int x = v;
    #pragma unroll
    for (int off = 1; off < 32; off <<= 1) {
        int t = __shfl_up_sync(0xffffffffu, x, off);
        if (lane >= off) x += t;
    }
    if (lane == 31) ws[warp] = x;
    __syncthreads();
    if (warp == 0 && lane < 8) {
        int s = ws[lane];
        #pragma unroll
        for (int off = 1; off < 8; off <<= 1) {
            int t = __shfl_up_sync(0xffu, s, off);
            if (lane >= off) s += t;
        }
        ws[lane] = s;
    }
    __syncthreads();
    int excl = (warp ? ws[warp - 1] : 0) + x - v;
    if (tid < SCAN_NB) g_blkoff[tid] = excl;
    if (tid == 255) g_rowptr[N_NODES] = (warp ? ws[warp - 1] : 0) + x;
}

// scan stage C: per-block exclusive scan + block offset -> rowptr, wrcur
__global__ void __launch_bounds__(256) k_scanC() {
    __shared__ int ws[8];
    int i = blockIdx.x * 256 + threadIdx.x;
    int tid = threadIdx.x;
    int lane = tid & 31, warp = tid >> 5;
    int v = (i < N_NODES) ? g_deg[i] : 0;
    int x = v;
    #pragma unroll
    for (int off = 1; off < 32; off <<= 1) {
        int t = __shfl_up_sync(0xffffffffu, x, off);
        if (lane >= off) x += t;
    }
    if (lane == 31) ws[warp] = x;
    __syncthreads();
    if (warp == 0 && lane < 8) {
        int s = ws[lane];
        #pragma unroll
        for (int off = 1; off < 8; off <<= 1) {
            int t = __shfl_up_sync(0xffu, s, off);
            if (lane >= off) s += t;
        }
        ws[lane] = s;
    }
    __syncthreads();
    int excl = g_blkoff[blockIdx.x] + (warp ? ws[warp - 1] : 0) + x - v;
    if (i < N_NODES) { g_rowptr[i] = excl; g_wrcur[i] = excl; }
}

__global__ void k_fill(const void* __restrict__ ei) {
    int e = blockIdx.x * 256 + threadIdx.x;
    if (e >= E_TOT) return;
    int s, d;
    if (e < E_EDGES) {
        s = load_idx(ei, 0, e);
        d = load_idx(ei, 1, e);
    } else {
        s = d = e - E_EDGES;
    }
    if ((unsigned)s >= N_NODES || (unsigned)d >= N_NODES) return;
    int pos = atomicAdd(&g_wrcur[d], 1);
    if ((unsigned)pos < E_TOT) g_csrc[pos] = s;
}

// ---------------- GEMM: C[N,256] = A[N,K] @ W[K,256], C stored fp16 ---------
// BM=64, BN=128, BK=16, 256 threads, per-thread 4x8 micro-tile (as 4x4 f32x2)
__global__ void __launch_bounds__(256) k_gemm(const float* __restrict__ xin,
                                              int use_feat,
                                              const float* __restrict__ W,
                                              int M, int K) {
    const float* A = use_feat ? g_feat : xin;
    __shared__ float As[16][65];
    __shared__ float Bs[16][128];
    int tid = threadIdx.x;
    int tx = tid & 15;   // n-group
    int ty = tid >> 4;   // m-group
    int bm = blockIdx.y * 64;
    int bn = blockIdx.x * 128;

    unsigned long long c[4][4];
    #pragma unroll
    for (int i = 0; i < 4; i++)
        #pragma unroll
        for (int j = 0; j < 4; j++) c[i][j] = 0ull;

    int arow = tid >> 2;            // 0..63
    int acol = (tid & 3) * 4;       // 0,4,8,12
    int bk   = tid >> 4;            // 0..15
    int bnc  = (tid & 15) * 8;      // 0..120

    for (int k0 = 0; k0 < K; k0 += 16) {
        float4 av = make_float4(0.f, 0.f, 0.f, 0.f);
        int gr = bm + arow;
        if (gr < M) av = *(const float4*)(A + (size_t)gr * K + k0 + acol);
        As[acol + 0][arow] = av.x;
        As[acol + 1][arow] = av.y;
        As[acol + 2][arow] = av.z;
        As[acol + 3][arow] = av.w;

        const float* bp = W + (size_t)(k0 + bk) * FDIM + bn + bnc;
        *(float4*)&Bs[bk][bnc]     = *(const float4*)bp;
        *(float4*)&Bs[bk][bnc + 4] = *(const float4*)(bp + 4);
        __syncthreads();

        #pragma unroll
        for (int k = 0; k < 16; k++) {
            unsigned long long aP[4];
            #pragma unroll
            for (int i = 0; i < 4; i++) aP[i] = pack2(As[k][ty * 4 + i]);
            unsigned long long bq[4];
            #pragma unroll
            for (int j = 0; j < 4; j++)
                bq[j] = *(const unsigned long long*)&Bs[k][tx * 2 + 32 * j];
            #pragma unroll
            for (int i = 0; i < 4; i++)
                #pragma unroll
                for (int j = 0; j < 4; j++) ffma2(c[i][j], aP[i], bq[j]);
        }
        __syncthreads();
    }

    __half2* hb = (__half2*)g_hbuf;
    #pragma unroll
    for (int i = 0; i < 4; i++) {
        int gr = bm + ty * 4 + i;
        if (gr < M) {
            #pragma unroll
            for (int j = 0; j < 4; j++) {
                float lo, hi;
                unpack2(c[i][j], lo, hi);
                int col = bn + tx * 2 + 32 * j;   // even
                hb[(size_t)gr * FDIM2 + (col >> 1)] = __floats2half2_rn(lo, hi);
            }
        }
    }
}

// ---------------- attention logits: als/ald [N,4] ----------------
__global__ void __launch_bounds__(128) k_attn(const float* __restrict__ asrc,
                                              const float* __restrict__ adst) {
    int v = blockIdx.x;
    int tid = threadIdx.x;
    int h = tid >> 5, lane = tid & 31;
    const __half2* hb = (const __half2*)g_hbuf + (size_t)v * FDIM2 + h * 32;
    float2 x = __half22float2(hb[lane]);
    int base = h * HID + lane * 2;
    float s = x.x * asrc[base] + x.y * asrc[base + 1];
    float d = x.x * adst[base] + x.y * adst[base + 1];
    #pragma unroll
    for (int off = 16; off >= 1; off >>= 1) {
        s += __shfl_xor_sync(0xffffffffu, s, off);
        d += __shfl_xor_sync(0xffffffffu, d, off);
    }
    if (lane == 0) {
        g_als[v * HEADS + h] = s;
        g_ald[v * HEADS + h] = d;
    }
}

// ---------------- softmax + aggregation: one block (128 thr) per dst node ---
__global__ void __launch_bounds__(128) k_agg(const float* __restrict__ bias) {
    int v = blockIdx.x;
    int tid = threadIdx.x, lane = tid & 31, warp = tid >> 5;
    int beg = g_rowptr[v];
    int deg = g_rowptr[v + 1] - beg;

    __shared__ float  s_mred[4][4], s_tred[4][4];   // [warp][head]
    __shared__ float  s_m[4], s_inv[4];
    __shared__ int    s_src[128];
    __shared__ float4 s_alpha[128];
    __shared__ float2 s_acc[128];

    float4 aldv = *(const float4*)(g_ald + v * 4);

    // ---- single online-softmax pass: per-head running (max, sum) ----
    float m0 = -1e30f, m1 = -1e30f, m2 = -1e30f, m3 = -1e30f;
    float t0 = 0.f, t1 = 0.f, t2 = 0.f, t3 = 0.f;
    for (int j = tid; j < deg; j += 128) {
        float4 as = *(const float4*)(g_als + g_csrc[beg + j] * 4);
        float e0 = lrelu(as.x + aldv.x), e1 = lrelu(as.y + aldv.y);
        float e2 = lrelu(as.z + aldv.z), e3 = lrelu(as.w + aldv.w);
        float n0 = fmaxf(m0, e0), n1 = fmaxf(m1, e1);
        float n2 = fmaxf(m2, e2), n3 = fmaxf(m3, e3);
        t0 = t0 * __expf(m0 - n0) + __expf(e0 - n0);
        t1 = t1 * __expf(m1 - n1) + __expf(e1 - n1);
        t2 = t2 * __expf(m2 - n2) + __expf(e2 - n2);
        t3 = t3 * __expf(m3 - n3) + __expf(e3 - n3);
        m0 = n0; m1 = n1; m2 = n2; m3 = n3;
    }
    #pragma unroll
    for (int off = 16; off >= 1; off >>= 1) {
        float om, ot, nm;
        om = __shfl_xor_sync(0xffffffffu, m0, off); ot = __shfl_xor_sync(0xffffffffu, t0, off);
        nm = fmaxf(m0, om); t0 = t0 * __expf(m0 - nm) + ot * __expf(om - nm); m0 = nm;
        om = __shfl_xor_sync(0xffffffffu, m1, off); ot = __shfl_xor_sync(0xffffffffu, t1, off);
        nm = fmaxf(m1, om); t1 = t1 * __expf(m1 - nm) + ot * __expf(om - nm); m1 = nm;
        om = __shfl_xor_sync(0xffffffffu, m2, off); ot = __shfl_xor_sync(0xffffffffu, t2, off);
        nm = fmaxf(m2, om); t2 = t2 * __expf(m2 - nm) + ot * __expf(om - nm); m2 = nm;
        om = __shfl_xor_sync(0xffffffffu, m3, off); ot = __shfl_xor_sync(0xffffffffu, t3, off);
        nm = fmaxf(m3, om); t3 = t3 * __expf(m3 - nm) + ot * __expf(om - nm); m3 = nm;
    }
    if (lane == 0) {
        s_mred[warp][0] = m0; s_tred[warp][0] = t0;
        s_mred[warp][1] = m1; s_tred[warp][1] = t1;
        s_mred[warp][2] = m2; s_tred[warp][2] = t2;
        s_mred[warp][3] = m3; s_tred[warp][3] = t3;
    }
    __syncthreads();
    if (tid < 4) {
        float m = -1e30f;
        #pragma unroll
        for (int w = 0; w < 4; w++) m = fmaxf(m, s_mred[w][tid]);
        float t = 0.f;
        #pragma unroll
        for (int w = 0; w < 4; w++) t += s_tred[w][tid] * __expf(s_mred[w][tid] - m);
        s_m[tid] = m;
        s_inv[tid] = 1.f / t;
    }
    __syncthreads();
    m0 = s_m[0]; m1 = s_m[1]; m2 = s_m[2]; m3 = s_m[3];
    float i0 = s_inv[0], i1 = s_inv[1], i2 = s_inv[2], i3 = s_inv[3];

    // ---- aggregation: thread owns half2 channel c = tid (0..127) ----
    const __half2* hb = (const __half2*)g_hbuf;
    float2 acc = make_float2(0.f, 0.f);
    int c = tid;
    int hd = tid >> 5;   // head of this half2 channel
    for (int c0 = 0; c0 < deg; c0 += 128) {
        __syncthreads();
        int j = c0 + tid;
        if (j < deg) {
            int s = g_csrc[beg + j];
            float4 as = *(const float4*)(g_als + s * 4);
            float a0 = __expf(lrelu(as.x + aldv.x) - m0) * i0;
            float a1 = __expf(lrelu(as.y + aldv.y) - m1) * i1;
            float a2 = __expf(lrelu(as.z + aldv.z) - m2) * i2;
            float a3 = __expf(lrelu(as.w + aldv.w) - m3) * i3;
            s_src[tid] = s;
            s_alpha[tid] = make_float4(a0, a1, a2, a3);
        }
        __syncthreads();
        int nc = min(128, deg - c0);
        int jj = 0;
        for (; jj + 4 <= nc; jj += 4) {
            int sA = s_src[jj], sB = s_src[jj + 1], sC = s_src[jj + 2], sD = s_src[jj + 3];
            float aA = ((const float*)&s_alpha[jj])[hd];
            float aB = ((const float*)&s_alpha[jj + 1])[hd];
            float aC = ((const float*)&s_alpha[jj + 2])[hd];
            float aD = ((const float*)&s_alpha[jj + 3])[hd];
            float2 vA = __half22float2(hb[(size_t)sA * FDIM2 + c]);
            float2 vB = __half22float2(hb[(size_t)sB * FDIM2 + c]);
            float2 vC = __half22float2(hb[(size_t)sC * FDIM2 + c]);
            float2 vD = __half22float2(hb[(size_t)sD * FDIM2 + c]);
            acc.x = fmaf(aA, vA.x, acc.x); acc.y = fmaf(aA, vA.y, acc.y);
            acc.x = fmaf(aB, vB.x, acc.x); acc.y = fmaf(aB, vB.y, acc.y);
            acc.x = fmaf(aC, vC.x, acc.x); acc.y = fmaf(aC, vC.y, acc.y);
            acc.x = fmaf(aD, vD.x, acc.x); acc.y = fmaf(aD, vD.y, acc.y);
        }
        for (; jj < nc; jj++) {
            int s = s_src[jj];
            float a = ((const float*)&s_alpha[jj])[hd];
            float2 vv = __half22float2(hb[(size_t)s * FDIM2 + c]);
            acc.x = fmaf(a, vv.x, acc.x);
            acc.y = fmaf(a, vv.y, acc.y);
        }
    }
    s_acc[tid] = acc;
    __syncthreads();
    // mean over heads: threads {t, t+32, t+64, t+96} share within-head channel
    if (tid < 32) {
        float2 r = s_acc[tid];
        float2 r1 = s_acc[tid + 32], r2 = s_acc[tid + 64], r3 = s_acc[tid + 96];
        r.x += r1.x + r2.x + r3.x;
        r.y += r1.y + r2.y + r3.y;
        int d = tid * 2;
        float o0 = r.x * 0.25f + bias[d];
        float o1 = r.y * 0.25f + bias[d + 1];
        g_feat[(size_t)v * HID + d]     = o0 > 0.f ? o0 : expm1f(o0);
        g_feat[(size_t)v * HID + d + 1] = o1 > 0.f ? o1 : expm1f(o1);
    }
}

// ---------------- final FC: out[N,10] = feat @ fcW + fcb --------------------
__global__ void __launch_bounds__(256) k_fc(const float* __restrict__ W,
                                            const float* __restrict__ b,
                                            float* __restrict__ out) {
    __shared__ float sw[HID * OUTDIM];
    __shared__ float sb[OUTDIM];
    for (int i = threadIdx.x; i < HID * OUTDIM; i += 256) sw[i] = W[i];
    if (threadIdx.x < OUTDIM) sb[threadIdx.x] = b[threadIdx.x];
    __syncthreads();
    int t = blockIdx.x * 256 + threadIdx.x;
    if (t >= N_NODES * OUTDIM) return;
    int n = t / OUTDIM, o = t - n * OUTDIM;
    const float* f = g_feat + (size_t)n * HID;
    float acc = sb[o];
    #pragma unroll
    for (int k = 0; k < HID; k++) acc = fmaf(f[k], sw[k * OUTDIM + o], acc);
    out[t] = acc;
}

// ---------------- launch ----------------
extern "C" void kernel_launch(void* const* d_in, const int* in_sizes, int n_in,
                              void* d_out, int out_size) {
    const float* x   = (const float*)d_in[0];
    const void*  ei  = d_in[1];
    const float* Wl[3]   = { (const float*)d_in[2], (const float*)d_in[6],  (const float*)d_in[10] };
    const float* Asl[3]  = { (const float*)d_in[3], (const float*)d_in[7],  (const float*)d_in[11] };
    const float* Adl[3]  = { (const float*)d_in[4], (const float*)d_in[8],  (const float*)d_in[12] };
    const float* Bl[3]   = { (const float*)d_in[5], (const float*)d_in[9],  (const float*)d_in[13] };
    const float* fcW = (const float*)d_in[14];
    const float* fcb = (const float*)d_in[15];
    float* out = (float*)d_out;

    // dtype probe + CSR by destination (rebuilt every call; deterministic)
    k_probe<<<1, 256>>>(ei);
    k_deg_init<<<(N_NODES + 255) / 256, 256>>>();
    k_hist<<<(E_EDGES + 255) / 256, 256>>>(ei);
    k_scanA<<<SCAN_NB, 256>>>();
    k_scanB<<<1, 256>>>();
    k_scanC<<<SCAN_NB, 256>>>();
    k_fill<<<(E_TOT + 255) / 256, 256>>>(ei);

    for (int l = 0; l < 3; l++) {
        int K = (l == 0) ? INDIM : HID;
        dim3 g(FDIM / 128, (N_NODES + 63) / 64);
        k_gemm<<<g, 256>>>(x, l > 0 ? 1 : 0, Wl[l], N_NODES, K);
        k_attn<<<N_NODES, 128>>>(Asl[l], Adl[l]);
        k_agg<<<N_NODES, 128>>>(Bl[l]);
    }
    k_fc<<<(N_NODES * OUTDIM + 255) / 256, 256>>>(fcW, fcb, out);
}

// round 7
// speedup vs baseline: 1.4789x; 1.1265x over previous
#include <cuda_runtime.h>
#include <cuda_fp16.h>
#include <math.h>

#define N_NODES 50000
#define E_EDGES 800000
#define E_TOT   850000   // + self loops
#define HEADS   4
#define HID     64
#define FDIM    256      // HEADS*HID
#define FDIM2   128      // half2 elements per row
#define INDIM   128
#define OUTDIM  10
#define NEG_SLOPE 0.2f
#define SCAN_NB  ((N_NODES + 255) / 256)   // 196

// ---------------- scratch (device globals; no allocations allowed) ----------
static __device__ __align__(16) __half g_hbuf[N_NODES * FDIM];   // projected features [N,256] fp16
static __device__ __align__(16) __half g_feat16[N_NODES * HID];  // layer output [N,64] fp16
static __device__ __align__(16) __half g_xh[N_NODES * INDIM];    // x converted to fp16
static __device__ __align__(16) __half g_whT0[FDIM * INDIM];     // W0^T [256,128] fp16
static __device__ __align__(16) __half g_whT1[FDIM * HID];       // W1^T [256,64]
static __device__ __align__(16) __half g_whT2[FDIM * HID];       // W2^T [256,64]
static __device__ __align__(16) float  g_als[N_NODES * HEADS];
static __device__ __align__(16) float  g_ald[N_NODES * HEADS];
static __device__ int   g_rowptr[N_NODES + 1];
static __device__ int   g_wrcur[N_NODES];
static __device__ int   g_deg[N_NODES];
static __device__ int   g_csrc[E_TOT];
static __device__ int   g_blksum[SCAN_NB];
static __device__ int   g_blkoff[SCAN_NB];
static __device__ int   g_is64;

// ---------------- helpers ----------------
__device__ __forceinline__ float lrelu(float x) {
    return x >= 0.f ? x : NEG_SLOPE * x;
}

__device__ __forceinline__ int load_idx(const void* ei, int which, int e) {
    if (g_is64) {
        long long v = ((const long long*)ei)[(size_t)which * E_EDGES + e];
        return (int)v;
    } else {
        return ((const int*)ei)[(size_t)which * E_EDGES + e];
    }
}

__device__ __forceinline__ void mma16816(float c[4], const unsigned a[4], const unsigned b[2]) {
    asm volatile(
        "mma.sync.aligned.m16n8k16.row.col.f32.f16.f16.f32 "
        "{%0,%1,%2,%3}, {%4,%5,%6,%7}, {%8,%9}, {%0,%1,%2,%3};\n"
        : "+f"(c[0]), "+f"(c[1]), "+f"(c[2]), "+f"(c[3])
        : "r"(a[0]), "r"(a[1]), "r"(a[2]), "r"(a[3]), "r"(b[0]), "r"(b[1]));
}

// ---------------- convert: x -> fp16, W -> W^T fp16 ----------------
#define CVT_XB 6250   // 1,600,000 float4 / 256
__global__ void __launch_bounds__(256) k_cvt(const float* __restrict__ x,
                                             const float* __restrict__ W0,
                                             const float* __restrict__ W1,
                                             const float* __restrict__ W2) {
    int b = blockIdx.x;
    if (b < CVT_XB) {
        int i = b * 256 + threadIdx.x;   // float4 idx, total 1.6M
        float4 v = ((const float4*)x)[i];
        __half2* o = (__half2*)g_xh;
        o[i * 2]     = __floats2half2_rn(v.x, v.y);
        o[i * 2 + 1] = __floats2half2_rn(v.z, v.w);
    } else {
        int t = (b - CVT_XB) * 256 + threadIdx.x;
        if (t < FDIM * INDIM) {                      // layer 0: [n,k] <- W0[k*256+n]
            int n = t >> 7, k = t & 127;
            g_whT0[t] = __float2half(W0[k * FDIM + n]);
        } else if (t < FDIM * INDIM + FDIM * HID) {
            int u = t - FDIM * INDIM;
            int n = u >> 6, k = u & 63;
            g_whT1[u] = __float2half(W1[k * FDIM + n]);
        } else if (t < FDIM * INDIM + 2 * FDIM * HID) {
            int u = t - FDIM * INDIM - FDIM * HID;
            int n = u >> 6, k = u & 63;
            g_whT2[u] = __float2half(W2[k * FDIM + n]);
        }
    }
}

// ---------------- dtype probe ----------------
__global__ void k_probe(const void* __restrict__ ei) {
    __shared__ int bad;
    if (threadIdx.x == 0) bad = 0;
    __syncthreads();
    const long long* p = (const long long*)ei;
    long long v = p[threadIdx.x];
    if (v < 0 || v >= N_NODES) atomicOr(&bad, 1);
    __syncthreads();
    if (threadIdx.x == 0) g_is64 = bad ? 0 : 1;
}

// ---------------- CSR build ----------------
__global__ void k_deg_init() {
    int i = blockIdx.x * 256 + threadIdx.x;
    if (i < N_NODES) g_deg[i] = 1;   // self loop
}

__global__ void k_hist(const void* __restrict__ ei) {
    int e = blockIdx.x * 256 + threadIdx.x;
    if (e < E_EDGES) {
        int d = load_idx(ei, 1, e);
        if ((unsigned)d < N_NODES) atomicAdd(&g_deg[d], 1);
    }
}

__global__ void __launch_bounds__(256) k_scanA() {
    __shared__ int sm[8];
    int i = blockIdx.x * 256 + threadIdx.x;
    int v = (i < N_NODES) ? g_deg[i] : 0;
    int lane = threadIdx.x & 31, warp = threadIdx.x >> 5;
    #pragma unroll
    for (int off = 16; off >= 1; off >>= 1) v += __shfl_xor_sync(0xffffffffu, v, off);
    if (lane == 0) sm[warp] = v;
    __syncthreads();
    if (threadIdx.x == 0) {
        int s = 0;
        #pragma unroll
        for (int w = 0; w < 8; w++) s += sm[w];
        g_blksum[blockIdx.x] = s;
    }
}

__global__ void __launch_bounds__(256) k_scanB() {
    __shared__ int ws[8];
    int tid = threadIdx.x;
    int lane = tid & 31, warp = tid >> 5;
    int v = (tid < SCAN_NB) ? g_blksum[tid] : 0;
    int x = v;
    #pragma unroll
    for (int off = 1; off < 32; off <<= 1) {
        int t = __shfl_up_sync(0xffffffffu, x, off);
        if (lane >= off) x += t;
    }
    if (lane == 31) ws[warp] = x;
    __syncthreads();
    if (warp == 0 && lane < 8) {
        int s = ws[lane];
        #pragma unroll
        for (int off = 1; off < 8; off <<= 1) {
            int t = __shfl_up_sync(0xffu, s, off);
            if (lane >= off) s += t;
        }
        ws[lane] = s;
    }
    __syncthreads();
    int excl = (warp ? ws[warp - 1] : 0) + x - v;
    if (tid < SCAN_NB) g_blkoff[tid] = excl;
    if (tid == 255) g_rowptr[N_NODES] = (warp ? ws[warp - 1] : 0) + x;
}

__global__ void __launch_bounds__(256) k_scanC() {
    __shared__ int ws[8];
    int i = blockIdx.x * 256 + threadIdx.x;
    int tid = threadIdx.x;
    int lane = tid & 31, warp = tid >> 5;
    int v = (i < N_NODES) ? g_deg[i] : 0;
    int x = v;
    #pragma unroll
    for (int off = 1; off < 32; off <<= 1) {
        int t = __shfl_up_sync(0xffffffffu, x, off);
        if (lane >= off) x += t;
    }
    if (lane == 31) ws[warp] = x;
    __syncthreads();
    if (warp == 0 && lane < 8) {
        int s = ws[lane];
        #pragma unroll
        for (int off = 1; off < 8; off <<= 1) {
            int t = __shfl_up_sync(0xffu, s, off);
            if (lane >= off) s += t;
        }
        ws[lane] = s;
    }
    __syncthreads();
    int excl = g_blkoff[blockIdx.x] + (warp ? ws[warp - 1] : 0) + x - v;
    if (i < N_NODES) { g_rowptr[i] = excl; g_wrcur[i] = excl; }
}

__global__ void k_fill(const void* __restrict__ ei) {
    int e = blockIdx.x * 256 + threadIdx.x;
    if (e >= E_TOT) return;
    int s, d;
    if (e < E_EDGES) {
        s = load_idx(ei, 0, e);
        d = load_idx(ei, 1, e);
    } else {
        s = d = e - E_EDGES;
    }
    if ((unsigned)s >= N_NODES || (unsigned)d >= N_NODES) return;
    int pos = atomicAdd(&g_wrcur[d], 1);
    if ((unsigned)pos < E_TOT) g_csrc[pos] = s;
}

// ---------------- GEMM (fp16 HMMA): hbuf[M,256] = A[M,K] @ Bt^T ------------
// asel: 0 -> g_xh, 1 -> g_feat16. bsel: 0/1/2 -> g_whT{0,1,2}.
// BM=128, BN=128, BK=16; 256 thr = 8 warps in 4(m) x 2(n); warp tile 32x64.
__global__ void __launch_bounds__(256) k_gemm_h(int asel, int bsel, int M, int K) {
    const __half* A  = asel ? g_feat16 : g_xh;
    const __half* Bt = (bsel == 0) ? g_whT0 : (bsel == 1 ? g_whT1 : g_whT2);

    __shared__ __half As[128][16];
    __shared__ __half Bs[128][16];
    int tid  = threadIdx.x;
    int warp = tid >> 5, lane = tid & 31;
    int wm = warp >> 1, wn = warp & 1;
    int g = lane >> 2, tig = lane & 3;
    int bm = blockIdx.y * 128, bn = blockIdx.x * 128;

    float acc[2][8][4];
    #pragma unroll
    for (int mi = 0; mi < 2; mi++)
        #pragma unroll
        for (int ni = 0; ni < 8; ni++)
            #pragma unroll
            for (int q = 0; q < 4; q++) acc[mi][ni][q] = 0.f;

    int lr = tid >> 1;           // 0..127
    int lc = (tid & 1) * 8;      // 0 or 8

    for (int k0 = 0; k0 < K; k0 += 16) {
        uint4 av = make_uint4(0, 0, 0, 0);
        int gr = bm + lr;
        if (gr < M) av = *(const uint4*)(A + (size_t)gr * K + k0 + lc);
        *(uint4*)&As[lr][lc] = av;
        *(uint4*)&Bs[lr][lc] = *(const uint4*)(Bt + (size_t)(bn + lr) * K + k0 + lc);
        __syncthreads();

        unsigned a[2][4], b[8][2];
        #pragma unroll
        for (int mi = 0; mi < 2; mi++) {
            int r0 = wm * 32 + mi * 16 + g;
            a[mi][0] = *(const unsigned*)&As[r0][2 * tig];
            a[mi][1] = *(const unsigned*)&As[r0 + 8][2 * tig];
            a[mi][2] = *(const unsigned*)&As[r0][2 * tig + 8];
            a[mi][3] = *(const unsigned*)&As[r0 + 8][2 * tig + 8];
        }
        #pragma unroll
        for (int ni = 0; ni < 8; ni++) {
            int n = wn * 64 + ni * 8 + g;
            b[ni][0] = *(const unsigned*)&Bs[n][2 * tig];
            b[ni][1] = *(const unsigned*)&Bs[n][2 * tig + 8];
        }
        #pragma unroll
        for (int mi = 0; mi < 2; mi++)
            #pragma unroll
            for (int ni = 0; ni < 8; ni++)
                mma16816(acc[mi][ni], a[mi], b[ni]);
        __syncthreads();
    }

    __half2* hb = (__half2*)g_hbuf;
    #pragma unroll
    for (int mi = 0; mi < 2; mi++) {
        int r0 = bm + wm * 32 + mi * 16 + g;
        #pragma unroll
        for (int ni = 0; ni < 8; ni++) {
            int c = bn + wn * 64 + ni * 8 + 2 * tig;   // even
            if (r0 < M)
                hb[(size_t)r0 * FDIM2 + (c >> 1)] = __floats2half2_rn(acc[mi][ni][0], acc[mi][ni][1]);
            if (r0 + 8 < M)
                hb[(size_t)(r0 + 8) * FDIM2 + (c >> 1)] = __floats2half2_rn(acc[mi][ni][2], acc[mi][ni][3]);
        }
    }
}

// ---------------- attention logits: als/ald [N,4] ----------------
__global__ void __launch_bounds__(128) k_attn(const float* __restrict__ asrc,
                                              const float* __restrict__ adst) {
    int v = blockIdx.x;
    int tid = threadIdx.x;
    int h = tid >> 5, lane = tid & 31;
    const __half2* hb = (const __half2*)g_hbuf + (size_t)v * FDIM2 + h * 32;
    float2 x = __half22float2(hb[lane]);
    int base = h * HID + lane * 2;
    float s = x.x * asrc[base] + x.y * asrc[base + 1];
    float d = x.x * adst[base] + x.y * adst[base + 1];
    #pragma unroll
    for (int off = 16; off >= 1; off >>= 1) {
        s += __shfl_xor_sync(0xffffffffu, s, off);
        d += __shfl_xor_sync(0xffffffffu, d, off);
    }
    if (lane == 0) {
        g_als[v * HEADS + h] = s;
        g_ald[v * HEADS + h] = d;
    }
}

// ---------------- softmax + aggregation: one block (128 thr) per dst node ---
// warp w processes edges j = c0+w, c0+w+4, ...; lane owns 8 channels (uint4).
__global__ void __launch_bounds__(128) k_agg(const float* __restrict__ bias) {
    int v = blockIdx.x;
    int tid = threadIdx.x, lane = tid & 31, warp = tid >> 5;
    int beg = g_rowptr[v];
    int deg = g_rowptr[v + 1] - beg;

    __shared__ float  s_mred[4][4], s_tred[4][4];
    __shared__ float  s_m[4], s_inv[4];
    __shared__ int    s_row[64];
    __shared__ float4 s_alpha[64];
    __shared__ float  s_acc[4][32][8];
    __shared__ float  s_out[FDIM];

    float4 aldv = *(const float4*)(g_ald + v * 4);

    // ---- online softmax over incoming edges (per head) ----
    float m0 = -1e30f, m1 = -1e30f, m2 = -1e30f, m3 = -1e30f;
    float t0 = 0.f, t1 = 0.f, t2 = 0.f, t3 = 0.f;
    for (int j = tid; j < deg; j += 128) {
        float4 as = *(const float4*)(g_als + g_csrc[beg + j] * 4);
        float e0 = lrelu(as.x + aldv.x), e1 = lrelu(as.y + aldv.y);
        float e2 = lrelu(as.z + aldv.z), e3 = lrelu(as.w + aldv.w);
        float n0 = fmaxf(m0, e0), n1 = fmaxf(m1, e1);
        float n2 = fmaxf(m2, e2), n3 = fmaxf(m3, e3);
        t0 = t0 * __expf(m0 - n0) + __expf(e0 - n0);
        t1 = t1 * __expf(m1 - n1) + __expf(e1 - n1);
        t2 = t2 * __expf(m2 - n2) + __expf(e2 - n2);
        t3 = t3 * __expf(m3 - n3) + __expf(e3 - n3);
        m0 = n0; m1 = n1; m2 = n2; m3 = n3;
    }
    #pragma unroll
    for (int off = 16; off >= 1; off >>= 1) {
        float om, ot, nm;
        om = __shfl_xor_sync(0xffffffffu, m0, off); ot = __shfl_xor_sync(0xffffffffu, t0, off);
        nm = fmaxf(m0, om); t0 = t0 * __expf(m0 - nm) + ot * __expf(om - nm); m0 = nm;
        om = __shfl_xor_sync(0xffffffffu, m1, off); ot = __shfl_xor_sync(0xffffffffu, t1, off);
        nm = fmaxf(m1, om); t1 = t1 * __expf(m1 - nm) + ot * __expf(om - nm); m1 = nm;
        om = __shfl_xor_sync(0xffffffffu, m2, off); ot = __shfl_xor_sync(0xffffffffu, t2, off);
        nm = fmaxf(m2, om); t2 = t2 * __expf(m2 - nm) + ot * __expf(om - nm); m2 = nm;
        om = __shfl_xor_sync(0xffffffffu, m3, off); ot = __shfl_xor_sync(0xffffffffu, t3, off);
        nm = fmaxf(m3, om); t3 = t3 * __expf(m3 - nm) + ot * __expf(om - nm); m3 = nm;
    }
    if (lane == 0) {
        s_mred[warp][0] = m0; s_tred[warp][0] = t0;
        s_mred[warp][1] = m1; s_tred[warp][1] = t1;
        s_mred[warp][2] = m2; s_tred[warp][2] = t2;
        s_mred[warp][3] = m3; s_tred[warp][3] = t3;
    }
    __syncthreads();
    if (tid < 4) {
        float m = -1e30f;
        #pragma unroll
        for (int w = 0; w < 4; w++) m = fmaxf(m, s_mred[w][tid]);
        float t = 0.f;
        #pragma unroll
        for (int w = 0; w < 4; w++) t += s_tred[w][tid] * __expf(s_mred[w][tid] - m);
        s_m[tid] = m;
        s_inv[tid] = 1.f / t;
    }
    __syncthreads();
    m0 = s_m[0]; m1 = s_m[1]; m2 = s_m[2]; m3 = s_m[3];
    float i0 = s_inv[0], i1 = s_inv[1], i2 = s_inv[2], i3 = s_inv[3];

    // ---- weighted aggregation ----
    const uint4* hb4 = (const uint4*)g_hbuf;   // 32 uint4 per row
    float acc[8];
    #pragma unroll
    for (int q = 0; q < 8; q++) acc[q] = 0.f;
    int hd = lane >> 3;   // head for this lane's 8-channel slice

    for (int c0 = 0; c0 < deg; c0 += 64) {
        __syncthreads();
        int j = c0 + tid;
        if (tid < 64 && j < deg) {
            int s = g_csrc[beg + j];
            float4 as = *(const float4*)(g_als + s * 4);
            s_row[tid] = s;
            s_alpha[tid] = make_float4(
                __expf(lrelu(as.x + aldv.x) - m0) * i0,
                __expf(lrelu(as.y + aldv.y) - m1) * i1,
                __expf(lrelu(as.z + aldv.z) - m2) * i2,
                __expf(lrelu(as.w + aldv.w) - m3) * i3);
        }
        __syncthreads();
        int nc = min(64, deg - c0);
        for (int j2 = warp; j2 < nc; j2 += 4) {
            int s = s_row[j2];
            float a = ((const float*)&s_alpha[j2])[hd];
            uint4 hv = hb4[(size_t)s * 32 + lane];
            const __half2* hp = (const __half2*)&hv;
            #pragma unroll
            for (int q = 0; q < 4; q++) {
                float2 f = __half22float2(hp[q]);
                acc[2 * q]     = fmaf(a, f.x, acc[2 * q]);
                acc[2 * q + 1] = fmaf(a, f.y, acc[2 * q + 1]);
            }
        }
    }
    #pragma unroll
    for (int q = 0; q < 8; q++) s_acc[warp][lane][q] = acc[q];
    __syncthreads();
    if (tid < 32) {
        #pragma unroll
        for (int q = 0; q < 8; q++) {
            float r = s_acc[0][tid][q] + s_acc[1][tid][q] + s_acc[2][tid][q] + s_acc[3][tid][q];
            s_out[tid * 8 + q] = r;
        }
    }
    __syncthreads();
    if (tid < HID) {
        float r = (s_out[tid] + s_out[tid + 64] + s_out[tid + 128] + s_out[tid + 192]) * 0.25f
                  + bias[tid];
        g_feat16[(size_t)v * HID + tid] = __float2half(r > 0.f ? r : expm1f(r));
    }
}

// ---------------- final FC: out[N,10] = feat16 @ fcW + fcb ------------------
__global__ void __launch_bounds__(256) k_fc(const float* __restrict__ W,
                                            const float* __restrict__ b,
                                            float* __restrict__ out) {
    __shared__ float sw[HID * OUTDIM];
    __shared__ float sb[OUTDIM];
    for (int i = threadIdx.x; i < HID * OUTDIM; i += 256) sw[i] = W[i];
    if (threadIdx.x < OUTDIM) sb[threadIdx.x] = b[threadIdx.x];
    __syncthreads();
    int t = blockIdx.x * 256 + threadIdx.x;
    if (t >= N_NODES * OUTDIM) return;
    int n = t / OUTDIM, o = t - n * OUTDIM;
    const __half* f = g_feat16 + (size_t)n * HID;
    float acc = sb[o];
    #pragma unroll
    for (int k = 0; k < HID; k++) acc = fmaf(__half2float(f[k]), sw[k * OUTDIM + o], acc);
    out[t] = acc;
}

// ---------------- launch ----------------
extern "C" void kernel_launch(void* const* d_in, const int* in_sizes, int n_in,
                              void* d_out, int out_size) {
    const float* x   = (const float*)d_in[0];
    const void*  ei  = d_in[1];
    const float* Wl[3]   = { (const float*)d_in[2], (const float*)d_in[6],  (const float*)d_in[10] };
    const float* Asl[3]  = { (const float*)d_in[3], (const float*)d_in[7],  (const float*)d_in[11] };
    const float* Adl[3]  = { (const float*)d_in[4], (const float*)d_in[8],  (const float*)d_in[12] };
    const float* Bl[3]   = { (const float*)d_in[5], (const float*)d_in[9],  (const float*)d_in[13] };
    const float* fcW = (const float*)d_in[14];
    const float* fcb = (const float*)d_in[15];
    float* out = (float*)d_out;

    int Kl[3] = { INDIM, HID, HID };

    // slot 1..3: converts + probe + deg init; slot 4: gemm0 (profiled)
    k_cvt<<<CVT_XB + 256, 256>>>(x, Wl[0], Wl[1], Wl[2]);
    k_probe<<<1, 256>>>(ei);
    k_deg_init<<<(N_NODES + 255) / 256, 256>>>();
    {
        dim3 g(FDIM / 128, (N_NODES + 127) / 128);
        k_gemm_h<<<g, 256>>>(0, 0, N_NODES, Kl[0]);
    }
    k_hist<<<(E_EDGES + 255) / 256, 256>>>(ei);
    k_scanA<<<SCAN_NB, 256>>>();
    k_scanB<<<1, 256>>>();
    k_scanC<<<SCAN_NB, 256>>>();
    k_fill<<<(E_TOT + 255) / 256, 256>>>(ei);

    k_attn<<<N_NODES, 128>>>(Asl[0], Adl[0]);
    k_agg<<<N_NODES, 128>>>(Bl[0]);

    for (int l = 1; l < 3; l++) {
        dim3 g(FDIM / 128, (N_NODES + 127) / 128);
        k_gemm_h<<<g, 256>>>(1, l, N_NODES, Kl[l]);
        k_attn<<<N_NODES, 128>>>(Asl[l], Adl[l]);
        k_agg<<<N_NODES, 128>>>(Bl[l]);
    }
    k_fc<<<(N_NODES * OUTDIM + 255) / 256, 256>>>(fcW, fcb, out);
}